// round 1
// baseline (speedup 1.0000x reference)
#include <cuda_runtime.h>
#include <math.h>

#define DD   1024
#define HH   16
#define DHH  64
#define BB   4
#define LL   512
#define TT   2048
#define EE   8
#define KKE  2
#define DFFN 4096
#define NL   (BB*LL)   /* 2048 latent tokens */
#define NT   (BB*TT)   /* 8192 context tokens */
#define BHN  (BB*HH)   /* 64 (b,h) pairs */
#define LN_EPS 1e-5f

// ---------------- scratch (device globals; no allocation allowed) ----------------
__device__ float g_lnq[(size_t)NL*DD];
__device__ float g_lnt[(size_t)NT*DD];
__device__ float g_qkv[(size_t)NL*3*DD];
__device__ float g_q2 [(size_t)NL*DD];
__device__ float g_kv [(size_t)NT*2*DD];
__device__ float g_scores[(size_t)BHN*LL*TT];
__device__ float g_attn[(size_t)NL*DD];
__device__ float g_x1 [(size_t)NL*DD];
__device__ float g_x2 [(size_t)NL*DD];
__device__ float g_h1 [(size_t)NL*KKE*DFFN];
__device__ float g_eo [(size_t)NL*KKE*DD];
__device__ int   g_idx [NL*KKE];
__device__ float g_gate[NL*KKE];
__device__ int   g_cnt[EE];
__device__ int   g_off[EE];
__device__ int   g_cur[EE];
__device__ int   g_rowlist[NL*KKE];
__device__ int   g_pairslot[NL*KKE];

// ---------------- helpers ----------------
__device__ __forceinline__ float blk_sum(float v) {
    __shared__ float sh[32];
    int lane = threadIdx.x & 31, w = threadIdx.x >> 5;
    #pragma unroll
    for (int o = 16; o; o >>= 1) v += __shfl_xor_sync(0xffffffffu, v, o);
    if (lane == 0) sh[w] = v;
    __syncthreads();
    if (w == 0) {
        float x = (lane < (int)(blockDim.x >> 5)) ? sh[lane] : 0.f;
        #pragma unroll
        for (int o = 16; o; o >>= 1) x += __shfl_xor_sync(0xffffffffu, x, o);
        if (lane == 0) sh[0] = x;
    }
    __syncthreads();
    float r = sh[0];
    __syncthreads();
    return r;
}

__device__ __forceinline__ float blk_max(float v) {
    __shared__ float sh[32];
    int lane = threadIdx.x & 31, w = threadIdx.x >> 5;
    #pragma unroll
    for (int o = 16; o; o >>= 1) v = fmaxf(v, __shfl_xor_sync(0xffffffffu, v, o));
    if (lane == 0) sh[w] = v;
    __syncthreads();
    if (w == 0) {
        float x = (lane < (int)(blockDim.x >> 5)) ? sh[lane] : -INFINITY;
        #pragma unroll
        for (int o = 16; o; o >>= 1) x = fmaxf(x, __shfl_xor_sync(0xffffffffu, x, o));
        if (lane == 0) sh[0] = x;
    }
    __syncthreads();
    float r = sh[0];
    __syncthreads();
    return r;
}

__device__ __forceinline__ float gelu_exact(float x) {
    return 0.5f * x * (1.f + erff(x * 0.70710678118654752f));
}

// ---------------- layernorm ----------------
__global__ void __launch_bounds__(256) ln_kernel(const float* __restrict__ x,
                                                 const float* __restrict__ g,
                                                 const float* __restrict__ b,
                                                 float* __restrict__ y) {
    size_t row = blockIdx.x;
    const float* xr = x + row * DD;
    float* yr = y + row * DD;
    int t = threadIdx.x;
    float v[4];
    float s = 0.f;
    #pragma unroll
    for (int i = 0; i < 4; i++) { v[i] = xr[t + 256 * i]; s += v[i]; }
    s = blk_sum(s);
    float mean = s * (1.f / DD);
    float s2 = 0.f;
    #pragma unroll
    for (int i = 0; i < 4; i++) { float d = v[i] - mean; s2 += d * d; }
    s2 = blk_sum(s2);
    float inv = rsqrtf(s2 * (1.f / DD) + LN_EPS);
    #pragma unroll
    for (int i = 0; i < 4; i++) {
        int c = t + 256 * i;
        yr[c] = (v[i] - mean) * inv * g[c] + b[c];
    }
}

// ---------------- generic NT GEMM ----------------
__global__ void __launch_bounds__(256) gemm_nt(const float* __restrict__ A, int lda,
                                               const float* __restrict__ W, int ldw,
                                               float* __restrict__ C, int ldc,
                                               const float* __restrict__ bias,
                                               const float* __restrict__ resid, int ldr,
                                               int Kd) {
    __shared__ float As[16][64];
    __shared__ float Bs[16][64];
    int row0 = blockIdx.y * 64, col0 = blockIdx.x * 64;
    int t = threadIdx.x;
    int an = t >> 2, ak = (t & 3) << 2;
    int ty = t >> 4, tx = t & 15;
    const float* Ap = A + (size_t)(row0 + an) * lda + ak;
    const float* Wp = W + (size_t)(col0 + an) * ldw + ak;
    float acc[4][4] = {};
    for (int k0 = 0; k0 < Kd; k0 += 16) {
        float4 av = *(const float4*)(Ap + k0);
        float4 wv = *(const float4*)(Wp + k0);
        As[ak + 0][an] = av.x; As[ak + 1][an] = av.y; As[ak + 2][an] = av.z; As[ak + 3][an] = av.w;
        Bs[ak + 0][an] = wv.x; Bs[ak + 1][an] = wv.y; Bs[ak + 2][an] = wv.z; Bs[ak + 3][an] = wv.w;
        __syncthreads();
        #pragma unroll
        for (int k = 0; k < 16; k++) {
            float4 a = *(const float4*)&As[k][ty << 2];
            float4 bq = *(const float4*)&Bs[k][tx << 2];
            float ar[4] = {a.x, a.y, a.z, a.w};
            float br[4] = {bq.x, bq.y, bq.z, bq.w};
            #pragma unroll
            for (int i = 0; i < 4; i++)
                #pragma unroll
                for (int j = 0; j < 4; j++)
                    acc[i][j] += ar[i] * br[j];
        }
        __syncthreads();
    }
    #pragma unroll
    for (int i = 0; i < 4; i++) {
        int r = row0 + (ty << 2) + i;
        #pragma unroll
        for (int j = 0; j < 4; j++) {
            int c = col0 + (tx << 2) + j;
            float v = acc[i][j];
            if (bias) v += bias[c];
            if (resid) v += resid[(size_t)r * ldr + c];
            C[(size_t)r * ldc + c] = v;
        }
    }
}

// ---------------- attention scores ----------------
__global__ void __launch_bounds__(256) attn_scores(const float* __restrict__ Q, int ldq, int qc0,
                                                   const float* __restrict__ Kx, int ldk, int kc0,
                                                   float* __restrict__ S, int Lq, int Lk,
                                                   float scale) {
    int bh = blockIdx.z;
    int b = bh >> 4, h = bh & 15;
    int row0 = blockIdx.y * 64, col0 = blockIdx.x * 64;
    const float* Qb = Q + (size_t)(b * Lq) * ldq + qc0 + h * DHH;
    const float* Kb = Kx + (size_t)(b * Lk) * ldk + kc0 + h * DHH;
    float* Sb = S + (size_t)bh * Lq * Lk;
    __shared__ float As[16][64];
    __shared__ float Bs[16][64];
    int t = threadIdx.x;
    int an = t >> 2, ak = (t & 3) << 2;
    int ty = t >> 4, tx = t & 15;
    float acc[4][4] = {};
    for (int k0 = 0; k0 < DHH; k0 += 16) {
        float4 av = *(const float4*)(Qb + (size_t)(row0 + an) * ldq + k0 + ak);
        float4 bv = *(const float4*)(Kb + (size_t)(col0 + an) * ldk + k0 + ak);
        As[ak + 0][an] = av.x; As[ak + 1][an] = av.y; As[ak + 2][an] = av.z; As[ak + 3][an] = av.w;
        Bs[ak + 0][an] = bv.x; Bs[ak + 1][an] = bv.y; Bs[ak + 2][an] = bv.z; Bs[ak + 3][an] = bv.w;
        __syncthreads();
        #pragma unroll
        for (int k = 0; k < 16; k++) {
            float4 a = *(const float4*)&As[k][ty << 2];
            float4 bq = *(const float4*)&Bs[k][tx << 2];
            float ar[4] = {a.x, a.y, a.z, a.w};
            float br[4] = {bq.x, bq.y, bq.z, bq.w};
            #pragma unroll
            for (int i = 0; i < 4; i++)
                #pragma unroll
                for (int j = 0; j < 4; j++)
                    acc[i][j] += ar[i] * br[j];
        }
        __syncthreads();
    }
    #pragma unroll
    for (int i = 0; i < 4; i++) {
        int r = row0 + (ty << 2) + i;
        #pragma unroll
        for (int j = 0; j < 4; j++) {
            int c = col0 + (tx << 2) + j;
            Sb[(size_t)r * Lk + c] = acc[i][j] * scale;
        }
    }
}

// ---------------- row softmax ----------------
__global__ void __launch_bounds__(256) softmax_rows(float* __restrict__ S, int Lk) {
    float* row = S + (size_t)blockIdx.x * Lk;
    int t = threadIdx.x;
    float m = -INFINITY;
    for (int j = t; j < Lk; j += 256) m = fmaxf(m, row[j]);
    m = blk_max(m);
    float s = 0.f;
    for (int j = t; j < Lk; j += 256) { float e = expf(row[j] - m); row[j] = e; s += e; }
    s = blk_sum(s);
    float inv = 1.0f / s;
    for (int j = t; j < Lk; j += 256) row[j] *= inv;
}

// ---------------- attn @ V ----------------
__global__ void __launch_bounds__(256) attn_av(const float* __restrict__ S,
                                               const float* __restrict__ V, int ldv, int vc0,
                                               float* __restrict__ O, int Lq, int Lk) {
    int bh = blockIdx.y;
    int b = bh >> 4, h = bh & 15;
    int row0 = blockIdx.x * 64;
    const float* Sb = S + (size_t)bh * Lq * Lk;
    const float* Vb = V + (size_t)(b * Lk) * ldv + vc0 + h * DHH;
    float* Ob = O + (size_t)(b * Lq) * DD + h * DHH;
    __shared__ float As[16][64];
    __shared__ float Bs[16][64];
    int t = threadIdx.x;
    int ai = t >> 2, aj = (t & 3) << 2;
    int bjj = t >> 4, bd = (t & 15) << 2;
    int ty = t >> 4, tx = t & 15;
    float acc[4][4] = {};
    for (int j0 = 0; j0 < Lk; j0 += 16) {
        float4 av = *(const float4*)(Sb + (size_t)(row0 + ai) * Lk + j0 + aj);
        As[aj + 0][ai] = av.x; As[aj + 1][ai] = av.y; As[aj + 2][ai] = av.z; As[aj + 3][ai] = av.w;
        float4 bv = *(const float4*)(Vb + (size_t)(j0 + bjj) * ldv + bd);
        *(float4*)&Bs[bjj][bd] = bv;
        __syncthreads();
        #pragma unroll
        for (int k = 0; k < 16; k++) {
            float4 a = *(const float4*)&As[k][ty << 2];
            float4 bq = *(const float4*)&Bs[k][tx << 2];
            float ar[4] = {a.x, a.y, a.z, a.w};
            float br[4] = {bq.x, bq.y, bq.z, bq.w};
            #pragma unroll
            for (int i = 0; i < 4; i++)
                #pragma unroll
                for (int j = 0; j < 4; j++)
                    acc[i][j] += ar[i] * br[j];
        }
        __syncthreads();
    }
    #pragma unroll
    for (int i = 0; i < 4; i++) {
        int r = row0 + (ty << 2) + i;
        #pragma unroll
        for (int j = 0; j < 4; j++) {
            Ob[(size_t)r * DD + (tx << 2) + j] = acc[i][j];
        }
    }
}

// ---------------- MoE routing ----------------
__global__ void moe_zero() {
    if (threadIdx.x < EE) g_cnt[threadIdx.x] = 0;
}

__global__ void __launch_bounds__(256) router_topk(const float* __restrict__ H,
                                                   const float* __restrict__ rw,
                                                   const float* __restrict__ rb) {
    int warp = (blockIdx.x * blockDim.x + threadIdx.x) >> 5;
    int lane = threadIdx.x & 31;
    if (warp >= NL) return;
    const float* h = H + (size_t)warp * DD;
    float logit[EE];
    #pragma unroll
    for (int e = 0; e < EE; e++) {
        const float* w = rw + (size_t)e * DD;
        float s = 0.f;
        for (int d = lane; d < DD; d += 32) s += h[d] * w[d];
        #pragma unroll
        for (int o = 16; o; o >>= 1) s += __shfl_xor_sync(0xffffffffu, s, o);
        logit[e] = s + rb[e];
    }
    if (lane == 0) {
        int i0 = 0; float m0 = logit[0];
        #pragma unroll
        for (int e = 1; e < EE; e++) if (logit[e] > m0) { m0 = logit[e]; i0 = e; }
        int i1 = -1; float m1 = -INFINITY;
        #pragma unroll
        for (int e = 0; e < EE; e++) if (e != i0 && logit[e] > m1) { m1 = logit[e]; i1 = e; }
        float z = expf(m1 - m0);
        float inv = 1.f / (1.f + z);
        g_idx[warp * 2] = i0;  g_idx[warp * 2 + 1] = i1;
        g_gate[warp * 2] = inv; g_gate[warp * 2 + 1] = z * inv;
        atomicAdd(&g_cnt[i0], 1);
        atomicAdd(&g_cnt[i1], 1);
    }
}

__global__ void moe_offsets() {
    if (threadIdx.x == 0) {
        int s = 0;
        for (int e = 0; e < EE; e++) { g_off[e] = s; s += g_cnt[e]; g_cur[e] = 0; }
    }
}

__global__ void __launch_bounds__(256) moe_assign() {
    int n = blockIdx.x * blockDim.x + threadIdx.x;
    if (n >= NL) return;
    #pragma unroll
    for (int k = 0; k < KKE; k++) {
        int e = g_idx[n * 2 + k];
        int pos = atomicAdd(&g_cur[e], 1);
        int slot = g_off[e] + pos;
        g_rowlist[slot] = n;
        g_pairslot[n * 2 + k] = slot;
    }
}

// ---------------- MoE grouped GEMM ----------------
__global__ void __launch_bounds__(256) moe_gemm(const float* __restrict__ A, int lda, int gather,
                                                const float* __restrict__ W,
                                                const float* __restrict__ bias,
                                                int M, int Kd,
                                                float* __restrict__ C, int ldc, int act) {
    int e = blockIdx.z;
    int count = g_cnt[e];
    int row0 = blockIdx.y * 64;
    if (row0 >= count) return;
    int base = g_off[e];
    const float* We = W + (size_t)e * M * Kd;
    const float* be = bias + (size_t)e * M;
    int col0 = blockIdx.x * 64;
    __shared__ float As[16][64];
    __shared__ float Bs[16][64];
    int t = threadIdx.x;
    int an = t >> 2, ak = (t & 3) << 2;
    int ty = t >> 4, tx = t & 15;
    int r = row0 + an;
    bool valid = r < count;
    const float* Ap;
    if (gather) {
        int tok = valid ? g_rowlist[base + r] : 0;
        Ap = A + (size_t)tok * lda + ak;
    } else {
        Ap = A + (size_t)(base + (valid ? r : 0)) * lda + ak;
    }
    const float* Wp = We + (size_t)(col0 + an) * Kd + ak;
    float acc[4][4] = {};
    for (int k0 = 0; k0 < Kd; k0 += 16) {
        float4 av = valid ? *(const float4*)(Ap + k0) : make_float4(0.f, 0.f, 0.f, 0.f);
        float4 wv = *(const float4*)(Wp + k0);
        As[ak + 0][an] = av.x; As[ak + 1][an] = av.y; As[ak + 2][an] = av.z; As[ak + 3][an] = av.w;
        Bs[ak + 0][an] = wv.x; Bs[ak + 1][an] = wv.y; Bs[ak + 2][an] = wv.z; Bs[ak + 3][an] = wv.w;
        __syncthreads();
        #pragma unroll
        for (int k = 0; k < 16; k++) {
            float4 a = *(const float4*)&As[k][ty << 2];
            float4 bq = *(const float4*)&Bs[k][tx << 2];
            float ar[4] = {a.x, a.y, a.z, a.w};
            float br[4] = {bq.x, bq.y, bq.z, bq.w};
            #pragma unroll
            for (int i = 0; i < 4; i++)
                #pragma unroll
                for (int j = 0; j < 4; j++)
                    acc[i][j] += ar[i] * br[j];
        }
        __syncthreads();
    }
    #pragma unroll
    for (int i = 0; i < 4; i++) {
        int rr = row0 + (ty << 2) + i;
        if (rr < count) {
            #pragma unroll
            for (int j = 0; j < 4; j++) {
                int c = col0 + (tx << 2) + j;
                float v = acc[i][j] + be[c];
                if (act) v = gelu_exact(v);
                C[(size_t)(base + rr) * ldc + c] = v;
            }
        }
    }
}

// ---------------- final mix ----------------
__global__ void __launch_bounds__(256) moe_mix(const float* __restrict__ x2,
                                               float* __restrict__ out) {
    int i = blockIdx.x * 256 + threadIdx.x;
    int n = i >> 10;
    int d = i & 1023;
    float v = x2[i];
    int s0 = g_pairslot[n * 2], s1 = g_pairslot[n * 2 + 1];
    v += g_gate[n * 2]     * g_eo[(size_t)s0 * DD + d];
    v += g_gate[n * 2 + 1] * g_eo[(size_t)s1 * DD + d];
    out[i] = v;
}

// ---------------- launch ----------------
extern "C" void kernel_launch(void* const* d_in, const int* in_sizes, int n_in,
                              void* d_out, int out_size) {
    const float* latents    = (const float*)d_in[0];
    const float* tokens     = (const float*)d_in[1];
    const float* sa_ln_g    = (const float*)d_in[2];
    const float* sa_ln_b    = (const float*)d_in[3];
    const float* sa_in_w    = (const float*)d_in[4];
    const float* sa_in_b    = (const float*)d_in[5];
    const float* sa_out_w   = (const float*)d_in[6];
    const float* sa_out_b   = (const float*)d_in[7];
    const float* ca_q_ln_g  = (const float*)d_in[8];
    const float* ca_q_ln_b  = (const float*)d_in[9];
    const float* ca_kv_ln_g = (const float*)d_in[10];
    const float* ca_kv_ln_b = (const float*)d_in[11];
    const float* ca_in_w    = (const float*)d_in[12];
    const float* ca_in_b    = (const float*)d_in[13];
    const float* ca_out_w   = (const float*)d_in[14];
    const float* ca_out_b   = (const float*)d_in[15];
    const float* moe_ln_g   = (const float*)d_in[16];
    const float* moe_ln_b   = (const float*)d_in[17];
    const float* router_w   = (const float*)d_in[18];
    const float* router_b   = (const float*)d_in[19];
    const float* e_fc1_w    = (const float*)d_in[20];
    const float* e_fc1_b    = (const float*)d_in[21];
    const float* e_fc2_w    = (const float*)d_in[22];
    const float* e_fc2_b    = (const float*)d_in[23];
    float* out = (float*)d_out;

    float *p_lnq, *p_lnt, *p_qkv, *p_q2, *p_kv, *p_s, *p_attn, *p_x1, *p_x2, *p_h1, *p_eo;
    cudaGetSymbolAddress((void**)&p_lnq,  g_lnq);
    cudaGetSymbolAddress((void**)&p_lnt,  g_lnt);
    cudaGetSymbolAddress((void**)&p_qkv,  g_qkv);
    cudaGetSymbolAddress((void**)&p_q2,   g_q2);
    cudaGetSymbolAddress((void**)&p_kv,   g_kv);
    cudaGetSymbolAddress((void**)&p_s,    g_scores);
    cudaGetSymbolAddress((void**)&p_attn, g_attn);
    cudaGetSymbolAddress((void**)&p_x1,   g_x1);
    cudaGetSymbolAddress((void**)&p_x2,   g_x2);
    cudaGetSymbolAddress((void**)&p_h1,   g_h1);
    cudaGetSymbolAddress((void**)&p_eo,   g_eo);

    const float scale = 0.125f;  // 1/sqrt(64)

    // ===== Self-attention =====
    ln_kernel<<<NL, 256>>>(latents, sa_ln_g, sa_ln_b, p_lnq);
    gemm_nt<<<dim3(48, 32), 256>>>(p_lnq, DD, sa_in_w, DD, p_qkv, 3 * DD,
                                   sa_in_b, nullptr, 0, DD);
    attn_scores<<<dim3(8, 8, BHN), 256>>>(p_qkv, 3 * DD, 0, p_qkv, 3 * DD, DD,
                                          p_s, LL, LL, scale);
    softmax_rows<<<BHN * LL, 256>>>(p_s, LL);
    attn_av<<<dim3(8, BHN), 256>>>(p_s, p_qkv, 3 * DD, 2 * DD, p_attn, LL, LL);
    gemm_nt<<<dim3(16, 32), 256>>>(p_attn, DD, sa_out_w, DD, p_x1, DD,
                                   sa_out_b, latents, DD, DD);

    // ===== Cross-attention =====
    ln_kernel<<<NL, 256>>>(p_x1, ca_q_ln_g, ca_q_ln_b, p_lnq);
    ln_kernel<<<NT, 256>>>(tokens, ca_kv_ln_g, ca_kv_ln_b, p_lnt);
    gemm_nt<<<dim3(16, 32), 256>>>(p_lnq, DD, ca_in_w, DD, p_q2, DD,
                                   ca_in_b, nullptr, 0, DD);
    gemm_nt<<<dim3(32, 128), 256>>>(p_lnt, DD, ca_in_w + (size_t)DD * DD, DD,
                                    p_kv, 2 * DD, ca_in_b + DD, nullptr, 0, DD);
    attn_scores<<<dim3(32, 8, BHN), 256>>>(p_q2, DD, 0, p_kv, 2 * DD, 0,
                                           p_s, LL, TT, scale);
    softmax_rows<<<BHN * LL, 256>>>(p_s, TT);
    attn_av<<<dim3(8, BHN), 256>>>(p_s, p_kv, 2 * DD, DD, p_attn, LL, TT);
    gemm_nt<<<dim3(16, 32), 256>>>(p_attn, DD, ca_out_w, DD, p_x2, DD,
                                   ca_out_b, p_x1, DD, DD);

    // ===== MoE (top-2 sparse) =====
    ln_kernel<<<NL, 256>>>(p_x2, moe_ln_g, moe_ln_b, p_lnq);
    moe_zero<<<1, 32>>>();
    router_topk<<<NL / 8, 256>>>(p_lnq, router_w, router_b);
    moe_offsets<<<1, 1>>>();
    moe_assign<<<NL / 256, 256>>>();
    moe_gemm<<<dim3(DFFN / 64, 32, EE), 256>>>(p_lnq, DD, 1, e_fc1_w, e_fc1_b,
                                               DFFN, DD, p_h1, DFFN, 1);
    moe_gemm<<<dim3(DD / 64, 32, EE), 256>>>(p_h1, DFFN, 0, e_fc2_w, e_fc2_b,
                                             DD, DFFN, p_eo, DD, 0);
    moe_mix<<<(NL * DD) / 256, 256>>>(p_x2, out);
}

// round 2
// speedup vs baseline: 2.7304x; 2.7304x over previous
#include <cuda_runtime.h>
#include <math.h>
#include <stdint.h>

#define DD   1024
#define HH   16
#define DHH  64
#define BB   4
#define LL   512
#define TT   2048
#define EE   8
#define KKE  2
#define DFFN 4096
#define NL   (BB*LL)
#define NT   (BB*TT)
#define BHN  (BB*HH)
#define LN_EPS 1e-5f

// ---------------- scratch ----------------
__device__ float g_lnq[(size_t)NL*DD];
__device__ float g_lnt[(size_t)NT*DD];
__device__ float g_qkv[(size_t)NL*3*DD];
__device__ float g_q2 [(size_t)NL*DD];
__device__ float g_kv [(size_t)NT*2*DD];
__device__ float g_scores[(size_t)BHN*LL*TT];
__device__ float g_attn[(size_t)NL*DD];
__device__ float g_x1 [(size_t)NL*DD];
__device__ float g_x2 [(size_t)NL*DD];
__device__ float g_h1 [(size_t)NL*KKE*DFFN];
__device__ float g_eo [(size_t)NL*KKE*DD];
__device__ int   g_idx [NL*KKE];
__device__ float g_gate[NL*KKE];
__device__ int   g_cnt[EE];
__device__ int   g_off[EE];
__device__ int   g_cur[EE];
__device__ int   g_rowlist[NL*KKE];
__device__ int   g_pairslot[NL*KKE];

// ---------------- small helpers ----------------
__device__ __forceinline__ float blk_sum(float v) {
    __shared__ float sh[32];
    int lane = threadIdx.x & 31, w = threadIdx.x >> 5;
    #pragma unroll
    for (int o = 16; o; o >>= 1) v += __shfl_xor_sync(0xffffffffu, v, o);
    if (lane == 0) sh[w] = v;
    __syncthreads();
    if (w == 0) {
        float x = (lane < (int)(blockDim.x >> 5)) ? sh[lane] : 0.f;
        #pragma unroll
        for (int o = 16; o; o >>= 1) x += __shfl_xor_sync(0xffffffffu, x, o);
        if (lane == 0) sh[0] = x;
    }
    __syncthreads();
    float r = sh[0];
    __syncthreads();
    return r;
}

__device__ __forceinline__ float blk_max(float v) {
    __shared__ float sh[32];
    int lane = threadIdx.x & 31, w = threadIdx.x >> 5;
    #pragma unroll
    for (int o = 16; o; o >>= 1) v = fmaxf(v, __shfl_xor_sync(0xffffffffu, v, o));
    if (lane == 0) sh[w] = v;
    __syncthreads();
    if (w == 0) {
        float x = (lane < (int)(blockDim.x >> 5)) ? sh[lane] : -INFINITY;
        #pragma unroll
        for (int o = 16; o; o >>= 1) x = fmaxf(x, __shfl_xor_sync(0xffffffffu, x, o));
        if (lane == 0) sh[0] = x;
    }
    __syncthreads();
    float r = sh[0];
    __syncthreads();
    return r;
}

__device__ __forceinline__ float gelu_exact(float x) {
    return 0.5f * x * (1.f + erff(x * 0.70710678118654752f));
}

// ---------------- tf32 mma primitives ----------------
__device__ __forceinline__ uint32_t f2tf(float f) {
    uint32_t u;
    asm("cvt.rna.tf32.f32 %0, %1;" : "=r"(u) : "f"(f));
    return u;
}

__device__ __forceinline__ void mma8(float* cr, const uint32_t* a, const uint32_t* b) {
    asm volatile(
        "mma.sync.aligned.m16n8k8.row.col.f32.tf32.tf32.f32 "
        "{%0,%1,%2,%3}, {%4,%5,%6,%7}, {%8,%9}, {%0,%1,%2,%3};"
        : "+f"(cr[0]), "+f"(cr[1]), "+f"(cr[2]), "+f"(cr[3])
        : "r"(a[0]), "r"(a[1]), "r"(a[2]), "r"(a[3]), "r"(b[0]), "r"(b[1]));
}

__device__ __forceinline__ void cp16(uint32_t dst, const void* src) {
    asm volatile("cp.async.cg.shared.global [%0], [%1], 16;" :: "r"(dst), "l"(src));
}
__device__ __forceinline__ void cp16p(uint32_t dst, const void* src, bool valid) {
    int sz = valid ? 16 : 0;
    asm volatile("cp.async.cg.shared.global [%0], [%1], 16, %2;" :: "r"(dst), "l"(src), "r"(sz));
}
__device__ __forceinline__ void cpcommit() { asm volatile("cp.async.commit_group;"); }
__device__ __forceinline__ void cpwait1() { asm volatile("cp.async.wait_group 1;"); }
__device__ __forceinline__ void cpwait0() { asm volatile("cp.async.wait_group 0;"); }

// compute one 32-k slab of warp tile. A layout: [m][36] k-major.
// BKN=false: B layout [n][36] k-major.  BKN=true: B layout [k][BST] n-major.
template<int WM, int WN, bool BKN, int BST>
__device__ __forceinline__ void mma_tile(const float* __restrict__ Ab,
                                         const float* __restrict__ Bb,
                                         int wm, int wn, int g, int c,
                                         float (&acc)[WM][WN][4]) {
    #pragma unroll
    for (int kk = 0; kk < 4; kk++) {
        const int k0 = kk * 8;
        uint32_t af[WM][4];
        #pragma unroll
        for (int mi = 0; mi < WM; mi++) {
            const float* Ar = Ab + (wm + mi * 16 + g) * 36 + k0 + c;
            af[mi][0] = f2tf(Ar[0]);
            af[mi][1] = f2tf(Ar[8 * 36]);
            af[mi][2] = f2tf(Ar[4]);
            af[mi][3] = f2tf(Ar[8 * 36 + 4]);
        }
        uint32_t bf[WN][2];
        #pragma unroll
        for (int ni = 0; ni < WN; ni++) {
            if (BKN) {
                const float* Br = Bb + (k0 + c) * BST + wn + ni * 8 + g;
                bf[ni][0] = f2tf(Br[0]);
                bf[ni][1] = f2tf(Br[4 * BST]);
            } else {
                const float* Br = Bb + (wn + ni * 8 + g) * BST + k0 + c;
                bf[ni][0] = f2tf(Br[0]);
                bf[ni][1] = f2tf(Br[4]);
            }
        }
        #pragma unroll
        for (int mi = 0; mi < WM; mi++)
            #pragma unroll
            for (int ni = 0; ni < WN; ni++)
                mma8(acc[mi][ni], af[mi], bf[ni]);
    }
}

#define TILE_AB (128*36)
#define GEMM_SMEM (4*TILE_AB*4)       /* 73728 B */
#define AV_SMEM ((2*TILE_AB + 2*32*68)*4)  /* 54272 B */

// ---------------- layernorm ----------------
__global__ void __launch_bounds__(256) ln_kernel(const float* __restrict__ x,
                                                 const float* __restrict__ g,
                                                 const float* __restrict__ b,
                                                 float* __restrict__ y) {
    size_t row = blockIdx.x;
    const float* xr = x + row * DD;
    float* yr = y + row * DD;
    int t = threadIdx.x;
    float v[4];
    float s = 0.f;
    #pragma unroll
    for (int i = 0; i < 4; i++) { v[i] = xr[t + 256 * i]; s += v[i]; }
    s = blk_sum(s);
    float mean = s * (1.f / DD);
    float s2 = 0.f;
    #pragma unroll
    for (int i = 0; i < 4; i++) { float d = v[i] - mean; s2 += d * d; }
    s2 = blk_sum(s2);
    float inv = rsqrtf(s2 * (1.f / DD) + LN_EPS);
    #pragma unroll
    for (int i = 0; i < 4; i++) {
        int cc = t + 256 * i;
        yr[cc] = (v[i] - mean) * inv * g[cc] + b[cc];
    }
}

// ---------------- tf32 GEMM: C[m,n] = A[m,:].W[n,:] + bias + resid ----------------
__global__ void __launch_bounds__(256) gemm_tf32(const float* __restrict__ A, int lda,
                                                 const float* __restrict__ W, int ldw,
                                                 float* __restrict__ C, int ldc,
                                                 const float* __restrict__ bias,
                                                 const float* __restrict__ resid, int ldr,
                                                 int Kd) {
    extern __shared__ float sm[];
    float* As = sm;
    float* Bs = sm + 2 * TILE_AB;
    int t = threadIdx.x;
    int row0 = blockIdx.y * 128, col0 = blockIdx.x * 128;
    int lrow = t >> 1, lcol = (t & 1) * 16;
    const float* Ag = A + (size_t)(row0 + lrow) * lda + lcol;
    const float* Wg = W + (size_t)(col0 + lrow) * ldw + lcol;
    uint32_t as0 = (uint32_t)__cvta_generic_to_shared(As) + (lrow * 36 + lcol) * 4;
    uint32_t bs0 = (uint32_t)__cvta_generic_to_shared(Bs) + (lrow * 36 + lcol) * 4;
    int warp = t >> 5, lane = t & 31, g = lane >> 2, c = lane & 3;
    int wm = (warp >> 2) * 64, wn = (warp & 3) * 32;
    float acc[4][4][4] = {};
    int KT = Kd >> 5;
    // prologue
    #pragma unroll
    for (int i = 0; i < 4; i++) cp16(as0 + i * 16, Ag + i * 4);
    #pragma unroll
    for (int i = 0; i < 4; i++) cp16(bs0 + i * 16, Wg + i * 4);
    cpcommit();
    for (int kt = 0; kt < KT; kt++) {
        int cb = kt & 1;
        if (kt + 1 < KT) {
            int nb = (kt + 1) & 1;
            const float* a = Ag + (kt + 1) * 32;
            const float* w = Wg + (kt + 1) * 32;
            #pragma unroll
            for (int i = 0; i < 4; i++) cp16(as0 + nb * TILE_AB * 4 + i * 16, a + i * 4);
            #pragma unroll
            for (int i = 0; i < 4; i++) cp16(bs0 + nb * TILE_AB * 4 + i * 16, w + i * 4);
            cpcommit();
            cpwait1();
        } else cpwait0();
        __syncthreads();
        mma_tile<4, 4, false, 36>(As + cb * TILE_AB, Bs + cb * TILE_AB, wm, wn, g, c, acc);
        __syncthreads();
    }
    #pragma unroll
    for (int mi = 0; mi < 4; mi++) {
        int r = row0 + wm + mi * 16 + g;
        #pragma unroll
        for (int ni = 0; ni < 4; ni++) {
            int cc = col0 + wn + ni * 8 + c * 2;
            float v0 = acc[mi][ni][0], v1 = acc[mi][ni][1];
            float v2 = acc[mi][ni][2], v3 = acc[mi][ni][3];
            if (bias) { float b0 = bias[cc], b1 = bias[cc + 1]; v0 += b0; v1 += b1; v2 += b0; v3 += b1; }
            if (resid) {
                const float* q0 = resid + (size_t)r * ldr + cc;
                const float* q1 = resid + (size_t)(r + 8) * ldr + cc;
                v0 += q0[0]; v1 += q0[1]; v2 += q1[0]; v3 += q1[1];
            }
            *(float2*)(C + (size_t)r * ldc + cc) = make_float2(v0, v1);
            *(float2*)(C + (size_t)(r + 8) * ldc + cc) = make_float2(v2, v3);
        }
    }
}

// ---------------- attention scores (tf32), batched over bh ----------------
__global__ void __launch_bounds__(256) attn_scores_tf32(const float* __restrict__ Q, int ldq, int qc0,
                                                        const float* __restrict__ Kx, int ldk, int kc0,
                                                        float* __restrict__ S, int Lq, int Lk,
                                                        float scale) {
    extern __shared__ float sm[];
    float* As = sm;
    float* Bs = sm + 2 * TILE_AB;
    int bh = blockIdx.z, b = bh >> 4, h = bh & 15;
    const float* Qb = Q + (size_t)(b * Lq) * ldq + qc0 + h * DHH;
    const float* Kb = Kx + (size_t)(b * Lk) * ldk + kc0 + h * DHH;
    float* Sb = S + (size_t)bh * Lq * Lk;
    int t = threadIdx.x;
    int row0 = blockIdx.y * 128, col0 = blockIdx.x * 128;
    int lrow = t >> 1, lcol = (t & 1) * 16;
    const float* Ag = Qb + (size_t)(row0 + lrow) * ldq + lcol;
    const float* Wg = Kb + (size_t)(col0 + lrow) * ldk + lcol;
    uint32_t as0 = (uint32_t)__cvta_generic_to_shared(As) + (lrow * 36 + lcol) * 4;
    uint32_t bs0 = (uint32_t)__cvta_generic_to_shared(Bs) + (lrow * 36 + lcol) * 4;
    int warp = t >> 5, lane = t & 31, g = lane >> 2, c = lane & 3;
    int wm = (warp >> 2) * 64, wn = (warp & 3) * 32;
    float acc[4][4][4] = {};
    const int KT = 2;  // dh=64
    #pragma unroll
    for (int i = 0; i < 4; i++) cp16(as0 + i * 16, Ag + i * 4);
    #pragma unroll
    for (int i = 0; i < 4; i++) cp16(bs0 + i * 16, Wg + i * 4);
    cpcommit();
    for (int kt = 0; kt < KT; kt++) {
        int cb = kt & 1;
        if (kt + 1 < KT) {
            int nb = (kt + 1) & 1;
            #pragma unroll
            for (int i = 0; i < 4; i++) cp16(as0 + nb * TILE_AB * 4 + i * 16, Ag + 32 + i * 4);
            #pragma unroll
            for (int i = 0; i < 4; i++) cp16(bs0 + nb * TILE_AB * 4 + i * 16, Wg + 32 + i * 4);
            cpcommit();
            cpwait1();
        } else cpwait0();
        __syncthreads();
        mma_tile<4, 4, false, 36>(As + cb * TILE_AB, Bs + cb * TILE_AB, wm, wn, g, c, acc);
        __syncthreads();
    }
    #pragma unroll
    for (int mi = 0; mi < 4; mi++) {
        int r = row0 + wm + mi * 16 + g;
        #pragma unroll
        for (int ni = 0; ni < 4; ni++) {
            int cc = col0 + wn + ni * 8 + c * 2;
            *(float2*)(Sb + (size_t)r * Lk + cc) =
                make_float2(acc[mi][ni][0] * scale, acc[mi][ni][1] * scale);
            *(float2*)(Sb + (size_t)(r + 8) * Lk + cc) =
                make_float2(acc[mi][ni][2] * scale, acc[mi][ni][3] * scale);
        }
    }
}

// ---------------- row softmax ----------------
__global__ void __launch_bounds__(256) softmax_rows(float* __restrict__ S, int Lk) {
    float* row = S + (size_t)blockIdx.x * Lk;
    int t = threadIdx.x;
    float m = -INFINITY;
    for (int j = t; j < Lk; j += 256) m = fmaxf(m, row[j]);
    m = blk_max(m);
    float s = 0.f;
    for (int j = t; j < Lk; j += 256) { float e = expf(row[j] - m); row[j] = e; s += e; }
    s = blk_sum(s);
    float inv = 1.0f / s;
    for (int j = t; j < Lk; j += 256) row[j] *= inv;
}

// ---------------- attn @ V (tf32), batched over bh, N=64 ----------------
__global__ void __launch_bounds__(256) attn_av_tf32(const float* __restrict__ S,
                                                    const float* __restrict__ V, int ldv, int vc0,
                                                    float* __restrict__ O, int Lq, int Lk) {
    extern __shared__ float sm[];
    float* As = sm;
    float* Bs = sm + 2 * TILE_AB;        // 2 x [32][68]
    const int BTILE = 32 * 68;
    int bh = blockIdx.y, b = bh >> 4, h = bh & 15;
    int row0 = blockIdx.x * 128;
    const float* Sb = S + (size_t)bh * Lq * Lk;
    const float* Vb = V + (size_t)(b * Lk) * ldv + vc0 + h * DHH;
    float* Ob = O + (size_t)(b * Lq) * DD + h * DHH;
    int t = threadIdx.x;
    int lrow = t >> 1, lcol = (t & 1) * 16;
    const float* Ag = Sb + (size_t)(row0 + lrow) * Lk + lcol;
    int krow = t >> 3, cseg = (t & 7) * 8;
    const float* Vg = Vb + (size_t)krow * ldv + cseg;
    uint32_t as0 = (uint32_t)__cvta_generic_to_shared(As) + (lrow * 36 + lcol) * 4;
    uint32_t bs0 = (uint32_t)__cvta_generic_to_shared(Bs) + (krow * 68 + cseg) * 4;
    int warp = t >> 5, lane = t & 31, g = lane >> 2, c = lane & 3;
    int wm = (warp >> 2) * 64, wn = (warp & 3) * 16;
    float acc[4][2][4] = {};
    int KT = Lk >> 5;
    #pragma unroll
    for (int i = 0; i < 4; i++) cp16(as0 + i * 16, Ag + i * 4);
    cp16(bs0, Vg);
    cp16(bs0 + 16, Vg + 4);
    cpcommit();
    for (int kt = 0; kt < KT; kt++) {
        int cb = kt & 1;
        if (kt + 1 < KT) {
            int nb = (kt + 1) & 1;
            const float* a = Ag + (kt + 1) * 32;
            const float* v = Vg + (size_t)(kt + 1) * 32 * ldv;
            #pragma unroll
            for (int i = 0; i < 4; i++) cp16(as0 + nb * TILE_AB * 4 + i * 16, a + i * 4);
            cp16(bs0 + nb * BTILE * 4, v);
            cp16(bs0 + nb * BTILE * 4 + 16, v + 4);
            cpcommit();
            cpwait1();
        } else cpwait0();
        __syncthreads();
        mma_tile<4, 2, true, 68>(As + cb * TILE_AB, Bs + cb * BTILE, wm, wn, g, c, acc);
        __syncthreads();
    }
    #pragma unroll
    for (int mi = 0; mi < 4; mi++) {
        int r = row0 + wm + mi * 16 + g;
        #pragma unroll
        for (int ni = 0; ni < 2; ni++) {
            int cc = wn + ni * 8 + c * 2;
            *(float2*)(Ob + (size_t)r * DD + cc) = make_float2(acc[mi][ni][0], acc[mi][ni][1]);
            *(float2*)(Ob + (size_t)(r + 8) * DD + cc) = make_float2(acc[mi][ni][2], acc[mi][ni][3]);
        }
    }
}

// ---------------- MoE routing ----------------
__global__ void moe_zero() {
    if (threadIdx.x < EE) g_cnt[threadIdx.x] = 0;
}

__global__ void __launch_bounds__(256) router_topk(const float* __restrict__ H,
                                                   const float* __restrict__ rw,
                                                   const float* __restrict__ rb) {
    int warp = (blockIdx.x * blockDim.x + threadIdx.x) >> 5;
    int lane = threadIdx.x & 31;
    if (warp >= NL) return;
    const float* h = H + (size_t)warp * DD;
    float logit[EE];
    #pragma unroll
    for (int e = 0; e < EE; e++) {
        const float* w = rw + (size_t)e * DD;
        float s = 0.f;
        for (int d = lane; d < DD; d += 32) s += h[d] * w[d];
        #pragma unroll
        for (int o = 16; o; o >>= 1) s += __shfl_xor_sync(0xffffffffu, s, o);
        logit[e] = s + rb[e];
    }
    if (lane == 0) {
        int i0 = 0; float m0 = logit[0];
        #pragma unroll
        for (int e = 1; e < EE; e++) if (logit[e] > m0) { m0 = logit[e]; i0 = e; }
        int i1 = -1; float m1 = -INFINITY;
        #pragma unroll
        for (int e = 0; e < EE; e++) if (e != i0 && logit[e] > m1) { m1 = logit[e]; i1 = e; }
        float z = expf(m1 - m0);
        float inv = 1.f / (1.f + z);
        g_idx[warp * 2] = i0;  g_idx[warp * 2 + 1] = i1;
        g_gate[warp * 2] = inv; g_gate[warp * 2 + 1] = z * inv;
        atomicAdd(&g_cnt[i0], 1);
        atomicAdd(&g_cnt[i1], 1);
    }
}

__global__ void moe_offsets() {
    if (threadIdx.x == 0) {
        int s = 0;
        for (int e = 0; e < EE; e++) { g_off[e] = s; s += g_cnt[e]; g_cur[e] = 0; }
    }
}

__global__ void __launch_bounds__(256) moe_assign() {
    int n = blockIdx.x * blockDim.x + threadIdx.x;
    if (n >= NL) return;
    #pragma unroll
    for (int k = 0; k < KKE; k++) {
        int e = g_idx[n * 2 + k];
        int pos = atomicAdd(&g_cur[e], 1);
        int slot = g_off[e] + pos;
        g_rowlist[slot] = n;
        g_pairslot[n * 2 + k] = slot;
    }
}

// ---------------- MoE grouped tf32 GEMM ----------------
__global__ void __launch_bounds__(256) moe_gemm_tf32(const float* __restrict__ A, int lda, int gather,
                                                     const float* __restrict__ W,
                                                     const float* __restrict__ bias,
                                                     int M, int Kd,
                                                     float* __restrict__ C, int ldc, int act) {
    extern __shared__ float sm[];
    float* As = sm;
    float* Bs = sm + 2 * TILE_AB;
    int e = blockIdx.z;
    int count = g_cnt[e];
    int row0 = blockIdx.y * 128;
    if (row0 >= count) return;
    int base = g_off[e];
    const float* We = W + (size_t)e * M * Kd;
    const float* be = bias + (size_t)e * M;
    int col0 = blockIdx.x * 128;
    int t = threadIdx.x;
    int lrow = t >> 1, lcol = (t & 1) * 16;
    int arow = row0 + lrow;
    bool valid = arow < count;
    int src;
    if (gather) src = g_rowlist[base + (valid ? arow : 0)];
    else        src = base + (valid ? arow : 0);
    const float* Ag = A + (size_t)src * lda + lcol;
    const float* Wg = We + (size_t)(col0 + lrow) * Kd + lcol;
    uint32_t as0 = (uint32_t)__cvta_generic_to_shared(As) + (lrow * 36 + lcol) * 4;
    uint32_t bs0 = (uint32_t)__cvta_generic_to_shared(Bs) + (lrow * 36 + lcol) * 4;
    int warp = t >> 5, lane = t & 31, g = lane >> 2, c = lane & 3;
    int wm = (warp >> 2) * 64, wn = (warp & 3) * 32;
    float acc[4][4][4] = {};
    int KT = Kd >> 5;
    #pragma unroll
    for (int i = 0; i < 4; i++) cp16p(as0 + i * 16, Ag + i * 4, valid);
    #pragma unroll
    for (int i = 0; i < 4; i++) cp16(bs0 + i * 16, Wg + i * 4);
    cpcommit();
    for (int kt = 0; kt < KT; kt++) {
        int cb = kt & 1;
        if (kt + 1 < KT) {
            int nb = (kt + 1) & 1;
            const float* a = Ag + (kt + 1) * 32;
            const float* w = Wg + (kt + 1) * 32;
            #pragma unroll
            for (int i = 0; i < 4; i++) cp16p(as0 + nb * TILE_AB * 4 + i * 16, a + i * 4, valid);
            #pragma unroll
            for (int i = 0; i < 4; i++) cp16(bs0 + nb * TILE_AB * 4 + i * 16, w + i * 4);
            cpcommit();
            cpwait1();
        } else cpwait0();
        __syncthreads();
        mma_tile<4, 4, false, 36>(As + cb * TILE_AB, Bs + cb * TILE_AB, wm, wn, g, c, acc);
        __syncthreads();
    }
    #pragma unroll
    for (int mi = 0; mi < 4; mi++) {
        int r = row0 + wm + mi * 16 + g;
        #pragma unroll
        for (int ni = 0; ni < 4; ni++) {
            int cc = col0 + wn + ni * 8 + c * 2;
            float b0 = be[cc], b1 = be[cc + 1];
            if (r < count) {
                float v0 = acc[mi][ni][0] + b0, v1 = acc[mi][ni][1] + b1;
                if (act) { v0 = gelu_exact(v0); v1 = gelu_exact(v1); }
                *(float2*)(C + (size_t)(base + r) * ldc + cc) = make_float2(v0, v1);
            }
            if (r + 8 < count) {
                float v2 = acc[mi][ni][2] + b0, v3 = acc[mi][ni][3] + b1;
                if (act) { v2 = gelu_exact(v2); v3 = gelu_exact(v3); }
                *(float2*)(C + (size_t)(base + r + 8) * ldc + cc) = make_float2(v2, v3);
            }
        }
    }
}

// ---------------- final mix ----------------
__global__ void __launch_bounds__(256) moe_mix(const float* __restrict__ x2,
                                               float* __restrict__ out) {
    int i = blockIdx.x * 256 + threadIdx.x;
    int n = i >> 10;
    int d = i & 1023;
    float v = x2[i];
    int s0 = g_pairslot[n * 2], s1 = g_pairslot[n * 2 + 1];
    v += g_gate[n * 2]     * g_eo[(size_t)s0 * DD + d];
    v += g_gate[n * 2 + 1] * g_eo[(size_t)s1 * DD + d];
    out[i] = v;
}

// ---------------- launch ----------------
extern "C" void kernel_launch(void* const* d_in, const int* in_sizes, int n_in,
                              void* d_out, int out_size) {
    const float* latents    = (const float*)d_in[0];
    const float* tokens     = (const float*)d_in[1];
    const float* sa_ln_g    = (const float*)d_in[2];
    const float* sa_ln_b    = (const float*)d_in[3];
    const float* sa_in_w    = (const float*)d_in[4];
    const float* sa_in_b    = (const float*)d_in[5];
    const float* sa_out_w   = (const float*)d_in[6];
    const float* sa_out_b   = (const float*)d_in[7];
    const float* ca_q_ln_g  = (const float*)d_in[8];
    const float* ca_q_ln_b  = (const float*)d_in[9];
    const float* ca_kv_ln_g = (const float*)d_in[10];
    const float* ca_kv_ln_b = (const float*)d_in[11];
    const float* ca_in_w    = (const float*)d_in[12];
    const float* ca_in_b    = (const float*)d_in[13];
    const float* ca_out_w   = (const float*)d_in[14];
    const float* ca_out_b   = (const float*)d_in[15];
    const float* moe_ln_g   = (const float*)d_in[16];
    const float* moe_ln_b   = (const float*)d_in[17];
    const float* router_w   = (const float*)d_in[18];
    const float* router_b   = (const float*)d_in[19];
    const float* e_fc1_w    = (const float*)d_in[20];
    const float* e_fc1_b    = (const float*)d_in[21];
    const float* e_fc2_w    = (const float*)d_in[22];
    const float* e_fc2_b    = (const float*)d_in[23];
    float* out = (float*)d_out;

    static int s_attr_done = 0;
    if (!s_attr_done) {
        cudaFuncSetAttribute(gemm_tf32, cudaFuncAttributeMaxDynamicSharedMemorySize, GEMM_SMEM);
        cudaFuncSetAttribute(attn_scores_tf32, cudaFuncAttributeMaxDynamicSharedMemorySize, GEMM_SMEM);
        cudaFuncSetAttribute(moe_gemm_tf32, cudaFuncAttributeMaxDynamicSharedMemorySize, GEMM_SMEM);
        cudaFuncSetAttribute(attn_av_tf32, cudaFuncAttributeMaxDynamicSharedMemorySize, AV_SMEM);
        s_attr_done = 1;
    }

    float *p_lnq, *p_lnt, *p_qkv, *p_q2, *p_kv, *p_s, *p_attn, *p_x1, *p_x2, *p_h1, *p_eo;
    cudaGetSymbolAddress((void**)&p_lnq,  g_lnq);
    cudaGetSymbolAddress((void**)&p_lnt,  g_lnt);
    cudaGetSymbolAddress((void**)&p_qkv,  g_qkv);
    cudaGetSymbolAddress((void**)&p_q2,   g_q2);
    cudaGetSymbolAddress((void**)&p_kv,   g_kv);
    cudaGetSymbolAddress((void**)&p_s,    g_scores);
    cudaGetSymbolAddress((void**)&p_attn, g_attn);
    cudaGetSymbolAddress((void**)&p_x1,   g_x1);
    cudaGetSymbolAddress((void**)&p_x2,   g_x2);
    cudaGetSymbolAddress((void**)&p_h1,   g_h1);
    cudaGetSymbolAddress((void**)&p_eo,   g_eo);

    const float scale = 0.125f;

    // ===== Self-attention =====
    ln_kernel<<<NL, 256>>>(latents, sa_ln_g, sa_ln_b, p_lnq);
    gemm_tf32<<<dim3(24, 16), 256, GEMM_SMEM>>>(p_lnq, DD, sa_in_w, DD, p_qkv, 3 * DD,
                                                sa_in_b, nullptr, 0, DD);
    attn_scores_tf32<<<dim3(4, 4, BHN), 256, GEMM_SMEM>>>(p_qkv, 3 * DD, 0, p_qkv, 3 * DD, DD,
                                                          p_s, LL, LL, scale);
    softmax_rows<<<BHN * LL, 256>>>(p_s, LL);
    attn_av_tf32<<<dim3(4, BHN), 256, AV_SMEM>>>(p_s, p_qkv, 3 * DD, 2 * DD, p_attn, LL, LL);
    gemm_tf32<<<dim3(8, 16), 256, GEMM_SMEM>>>(p_attn, DD, sa_out_w, DD, p_x1, DD,
                                               sa_out_b, latents, DD, DD);

    // ===== Cross-attention =====
    ln_kernel<<<NL, 256>>>(p_x1, ca_q_ln_g, ca_q_ln_b, p_lnq);
    ln_kernel<<<NT, 256>>>(tokens, ca_kv_ln_g, ca_kv_ln_b, p_lnt);
    gemm_tf32<<<dim3(8, 16), 256, GEMM_SMEM>>>(p_lnq, DD, ca_in_w, DD, p_q2, DD,
                                               ca_in_b, nullptr, 0, DD);
    gemm_tf32<<<dim3(16, 64), 256, GEMM_SMEM>>>(p_lnt, DD, ca_in_w + (size_t)DD * DD, DD,
                                                p_kv, 2 * DD, ca_in_b + DD, nullptr, 0, DD);
    attn_scores_tf32<<<dim3(16, 4, BHN), 256, GEMM_SMEM>>>(p_q2, DD, 0, p_kv, 2 * DD, 0,
                                                           p_s, LL, TT, scale);
    softmax_rows<<<BHN * LL, 256>>>(p_s, TT);
    attn_av_tf32<<<dim3(4, BHN), 256, AV_SMEM>>>(p_s, p_kv, 2 * DD, DD, p_attn, LL, TT);
    gemm_tf32<<<dim3(8, 16), 256, GEMM_SMEM>>>(p_attn, DD, ca_out_w, DD, p_x2, DD,
                                               ca_out_b, p_x1, DD, DD);

    // ===== MoE =====
    ln_kernel<<<NL, 256>>>(p_x2, moe_ln_g, moe_ln_b, p_lnq);
    moe_zero<<<1, 32>>>();
    router_topk<<<NL / 8, 256>>>(p_lnq, router_w, router_b);
    moe_offsets<<<1, 1>>>();
    moe_assign<<<NL / 256, 256>>>();
    moe_gemm_tf32<<<dim3(DFFN / 128, 16, EE), 256, GEMM_SMEM>>>(p_lnq, DD, 1, e_fc1_w, e_fc1_b,
                                                                DFFN, DD, p_h1, DFFN, 1);
    moe_gemm_tf32<<<dim3(DD / 128, 16, EE), 256, GEMM_SMEM>>>(p_h1, DFFN, 0, e_fc2_w, e_fc2_b,
                                                              DD, DFFN, p_eo, DD, 0);
    moe_mix<<<(NL * DD) / 256, 256>>>(p_x2, out);
}

// round 3
// speedup vs baseline: 3.0417x; 1.1140x over previous
#include <cuda_runtime.h>
#include <math.h>
#include <stdint.h>

#define DD   1024
#define HH   16
#define DHH  64
#define BB   4
#define LL   512
#define TT   2048
#define EE   8
#define KKE  2
#define DFFN 4096
#define NL   (BB*LL)
#define NT   (BB*TT)
#define BHN  (BB*HH)
#define LN_EPS 1e-5f

// ---------------- scratch ----------------
__device__ float g_lnq[(size_t)NL*DD];
__device__ float g_lnt[(size_t)NT*DD];
__device__ float g_qkv[(size_t)NL*3*DD];
__device__ float g_q2 [(size_t)NL*DD];
__device__ float g_kv [(size_t)NT*2*DD];
__device__ float g_attn[(size_t)NL*DD];
__device__ float g_x1 [(size_t)NL*DD];
__device__ float g_x2 [(size_t)NL*DD];
__device__ float g_h1 [(size_t)NL*KKE*DFFN];
__device__ float g_eo [(size_t)NL*KKE*DD];
__device__ int   g_idx [NL*KKE];
__device__ float g_gate[NL*KKE];
__device__ int   g_cnt[EE];
__device__ int   g_off[EE];
__device__ int   g_cur[EE];
__device__ int   g_rowlist[NL*KKE];
__device__ int   g_pairslot[NL*KKE];

// ---------------- helpers ----------------
__device__ __forceinline__ float blk_sum(float v) {
    __shared__ float sh[32];
    int lane = threadIdx.x & 31, w = threadIdx.x >> 5;
    #pragma unroll
    for (int o = 16; o; o >>= 1) v += __shfl_xor_sync(0xffffffffu, v, o);
    if (lane == 0) sh[w] = v;
    __syncthreads();
    if (w == 0) {
        float x = (lane < (int)(blockDim.x >> 5)) ? sh[lane] : 0.f;
        #pragma unroll
        for (int o = 16; o; o >>= 1) x += __shfl_xor_sync(0xffffffffu, x, o);
        if (lane == 0) sh[0] = x;
    }
    __syncthreads();
    float r = sh[0];
    __syncthreads();
    return r;
}

__device__ __forceinline__ float gelu_exact(float x) {
    return 0.5f * x * (1.f + erff(x * 0.70710678118654752f));
}

// ---------------- tf32 mma primitives ----------------
__device__ __forceinline__ uint32_t f2tf(float f) {
    uint32_t u;
    asm("cvt.rna.tf32.f32 %0, %1;" : "=r"(u) : "f"(f));
    return u;
}

__device__ __forceinline__ void mma8(float* cr, const uint32_t* a, const uint32_t* b) {
    asm volatile(
        "mma.sync.aligned.m16n8k8.row.col.f32.tf32.tf32.f32 "
        "{%0,%1,%2,%3}, {%4,%5,%6,%7}, {%8,%9}, {%0,%1,%2,%3};"
        : "+f"(cr[0]), "+f"(cr[1]), "+f"(cr[2]), "+f"(cr[3])
        : "r"(a[0]), "r"(a[1]), "r"(a[2]), "r"(a[3]), "r"(b[0]), "r"(b[1]));
}

__device__ __forceinline__ void cp16(uint32_t dst, const void* src) {
    asm volatile("cp.async.cg.shared.global [%0], [%1], 16;" :: "r"(dst), "l"(src));
}
__device__ __forceinline__ void cp16p(uint32_t dst, const void* src, bool valid) {
    int sz = valid ? 16 : 0;
    asm volatile("cp.async.cg.shared.global [%0], [%1], 16, %2;" :: "r"(dst), "l"(src), "r"(sz));
}
__device__ __forceinline__ void cpcommit() { asm volatile("cp.async.commit_group;"); }
__device__ __forceinline__ void cpwait1() { asm volatile("cp.async.wait_group 1;"); }
__device__ __forceinline__ void cpwait0() { asm volatile("cp.async.wait_group 0;"); }

// one 32-k slab. A layout [m][AST] k-major.
// BKN=false: B [n][BST] k-major.  BKN=true: B [k][BST] n-major.
template<int WM, int WN, bool BKN, int AST, int BST>
__device__ __forceinline__ void mma_tile(const float* __restrict__ Ab,
                                         const float* __restrict__ Bb,
                                         int wm, int wn, int g, int c,
                                         float (&acc)[WM][WN][4]) {
    #pragma unroll
    for (int kk = 0; kk < 4; kk++) {
        const int k0 = kk * 8;
        uint32_t af[WM][4];
        #pragma unroll
        for (int mi = 0; mi < WM; mi++) {
            const float* Ar = Ab + (wm + mi * 16 + g) * AST + k0 + c;
            af[mi][0] = f2tf(Ar[0]);
            af[mi][1] = f2tf(Ar[8 * AST]);
            af[mi][2] = f2tf(Ar[4]);
            af[mi][3] = f2tf(Ar[8 * AST + 4]);
        }
        uint32_t bf[WN][2];
        #pragma unroll
        for (int ni = 0; ni < WN; ni++) {
            if (BKN) {
                const float* Br = Bb + (k0 + c) * BST + wn + ni * 8 + g;
                bf[ni][0] = f2tf(Br[0]);
                bf[ni][1] = f2tf(Br[4 * BST]);
            } else {
                const float* Br = Bb + (wn + ni * 8 + g) * BST + k0 + c;
                bf[ni][0] = f2tf(Br[0]);
                bf[ni][1] = f2tf(Br[4]);
            }
        }
        #pragma unroll
        for (int mi = 0; mi < WM; mi++)
            #pragma unroll
            for (int ni = 0; ni < WN; ni++)
                mma8(acc[mi][ni], af[mi], bf[ni]);
    }
}

#define TILE_AB (128*36)
#define GEMM_SMEM (4*TILE_AB*4)

// ---------------- layernorm ----------------
__global__ void __launch_bounds__(256) ln_kernel(const float* __restrict__ x,
                                                 const float* __restrict__ g,
                                                 const float* __restrict__ b,
                                                 float* __restrict__ y) {
    size_t row = blockIdx.x;
    const float* xr = x + row * DD;
    float* yr = y + row * DD;
    int t = threadIdx.x;
    float v[4];
    float s = 0.f;
    #pragma unroll
    for (int i = 0; i < 4; i++) { v[i] = xr[t + 256 * i]; s += v[i]; }
    s = blk_sum(s);
    float mean = s * (1.f / DD);
    float s2 = 0.f;
    #pragma unroll
    for (int i = 0; i < 4; i++) { float d = v[i] - mean; s2 += d * d; }
    s2 = blk_sum(s2);
    float inv = rsqrtf(s2 * (1.f / DD) + LN_EPS);
    #pragma unroll
    for (int i = 0; i < 4; i++) {
        int cc = t + 256 * i;
        yr[cc] = (v[i] - mean) * inv * g[cc] + b[cc];
    }
}

// ---------------- tf32 GEMM ----------------
__global__ void __launch_bounds__(256, 2) gemm_tf32(const float* __restrict__ A, int lda,
                                                    const float* __restrict__ W, int ldw,
                                                    float* __restrict__ C, int ldc,
                                                    const float* __restrict__ bias,
                                                    const float* __restrict__ resid, int ldr,
                                                    int Kd) {
    extern __shared__ float sm[];
    float* As = sm;
    float* Bs = sm + 2 * TILE_AB;
    int t = threadIdx.x;
    int row0 = blockIdx.y * 128, col0 = blockIdx.x * 128;
    int lrow = t >> 1, lcol = (t & 1) * 16;
    const float* Ag = A + (size_t)(row0 + lrow) * lda + lcol;
    const float* Wg = W + (size_t)(col0 + lrow) * ldw + lcol;
    uint32_t as0 = (uint32_t)__cvta_generic_to_shared(As) + (lrow * 36 + lcol) * 4;
    uint32_t bs0 = (uint32_t)__cvta_generic_to_shared(Bs) + (lrow * 36 + lcol) * 4;
    int warp = t >> 5, lane = t & 31, g = lane >> 2, c = lane & 3;
    int wm = (warp >> 2) * 64, wn = (warp & 3) * 32;
    float acc[4][4][4] = {};
    int KT = Kd >> 5;
    #pragma unroll
    for (int i = 0; i < 4; i++) cp16(as0 + i * 16, Ag + i * 4);
    #pragma unroll
    for (int i = 0; i < 4; i++) cp16(bs0 + i * 16, Wg + i * 4);
    cpcommit();
    for (int kt = 0; kt < KT; kt++) {
        int cb = kt & 1;
        if (kt + 1 < KT) {
            int nb = (kt + 1) & 1;
            const float* a = Ag + (kt + 1) * 32;
            const float* w = Wg + (kt + 1) * 32;
            #pragma unroll
            for (int i = 0; i < 4; i++) cp16(as0 + nb * TILE_AB * 4 + i * 16, a + i * 4);
            #pragma unroll
            for (int i = 0; i < 4; i++) cp16(bs0 + nb * TILE_AB * 4 + i * 16, w + i * 4);
            cpcommit();
            cpwait1();
        } else cpwait0();
        __syncthreads();
        mma_tile<4, 4, false, 36, 36>(As + cb * TILE_AB, Bs + cb * TILE_AB, wm, wn, g, c, acc);
        __syncthreads();
    }
    #pragma unroll
    for (int mi = 0; mi < 4; mi++) {
        int r = row0 + wm + mi * 16 + g;
        #pragma unroll
        for (int ni = 0; ni < 4; ni++) {
            int cc = col0 + wn + ni * 8 + c * 2;
            float v0 = acc[mi][ni][0], v1 = acc[mi][ni][1];
            float v2 = acc[mi][ni][2], v3 = acc[mi][ni][3];
            if (bias) { float b0 = bias[cc], b1 = bias[cc + 1]; v0 += b0; v1 += b1; v2 += b0; v3 += b1; }
            if (resid) {
                const float* q0 = resid + (size_t)r * ldr + cc;
                const float* q1 = resid + (size_t)(r + 8) * ldr + cc;
                v0 += q0[0]; v1 += q0[1]; v2 += q1[0]; v3 += q1[1];
            }
            *(float2*)(C + (size_t)r * ldc + cc) = make_float2(v0, v1);
            *(float2*)(C + (size_t)(r + 8) * ldc + cc) = make_float2(v2, v3);
        }
    }
}

// ---------------- fused flash attention (tf32) ----------------
// Grid: (Lq/128, BHN). Block 256 (8 warps x 16 q-rows).
#define FA_N 64
#define FA_QS (128*68)
#define FA_KV (64*68)
#define FA_SMEM ((FA_QS + 4*FA_KV + FA_QS)*4)   /* 139264 B */

__global__ void __launch_bounds__(256) flash_tf32(const float* __restrict__ Q, int ldq,
                                                  const float* __restrict__ Kp, int ldk,
                                                  const float* __restrict__ Vp, int ldv,
                                                  float* __restrict__ O, int Lk, float scale) {
    extern __shared__ float sm[];
    float* Qs = sm;
    float* Ks = Qs + FA_QS;
    float* Vs = Ks + 2 * FA_KV;
    float* Ps = Vs + 2 * FA_KV;
    int bh = blockIdx.y, b = bh >> 4, h = bh & 15;
    int q0 = blockIdx.x * 128;
    int t = threadIdx.x;
    const float* Qg = Q + ((size_t)(b * LL + q0)) * ldq + h * DHH;
    const float* Kg = Kp + ((size_t)b * Lk) * ldk + h * DHH;
    const float* Vg = Vp + ((size_t)b * Lk) * ldv + h * DHH;
    uint32_t qs0 = (uint32_t)__cvta_generic_to_shared(Qs);
    uint32_t ks0 = (uint32_t)__cvta_generic_to_shared(Ks);
    uint32_t vs0 = (uint32_t)__cvta_generic_to_shared(Vs);
    // Q: 128 rows x 64 f -> 8 chunks/thread
    {
        int row = t >> 1, segb = (t & 1) * 8;
        const float* qr = Qg + (size_t)row * ldq;
        #pragma unroll
        for (int j = 0; j < 8; j++)
            cp16(qs0 + (row * 68 + (segb + j) * 4) * 4, qr + (segb + j) * 4);
    }
    int kr = t >> 2, kcb = (t & 3) * 16;   // 4 chunks per thread per tile
    // KV tile 0
    {
        const float* kg = Kg + (size_t)kr * ldk + kcb;
        const float* vg = Vg + (size_t)kr * ldv + kcb;
        uint32_t kb = ks0 + (kr * 68 + kcb) * 4;
        uint32_t vb = vs0 + (kr * 68 + kcb) * 4;
        #pragma unroll
        for (int j = 0; j < 4; j++) cp16(kb + j * 16, kg + j * 4);
        #pragma unroll
        for (int j = 0; j < 4; j++) cp16(vb + j * 16, vg + j * 4);
    }
    cpcommit();
    int warp = t >> 5, lane = t & 31, g = lane >> 2, c = lane & 3;
    int wr = warp * 16;
    float Oa[1][8][4] = {};
    float m0 = -INFINITY, m1 = -INFINITY, l0 = 0.f, l1 = 0.f;
    int niter = Lk / FA_N;
    for (int it = 0; it < niter; it++) {
        if (it + 1 < niter) {
            int buf = (it + 1) & 1;
            const float* kg = Kg + (size_t)((it + 1) * FA_N + kr) * ldk + kcb;
            const float* vg = Vg + (size_t)((it + 1) * FA_N + kr) * ldv + kcb;
            uint32_t kb = ks0 + (buf * FA_KV + kr * 68 + kcb) * 4;
            uint32_t vb = vs0 + (buf * FA_KV + kr * 68 + kcb) * 4;
            #pragma unroll
            for (int j = 0; j < 4; j++) cp16(kb + j * 16, kg + j * 4);
            #pragma unroll
            for (int j = 0; j < 4; j++) cp16(vb + j * 16, vg + j * 4);
            cpcommit();
            cpwait1();
        } else cpwait0();
        __syncthreads();
        const float* Kb = Ks + (it & 1) * FA_KV;
        const float* Vb = Vs + (it & 1) * FA_KV;
        float S[1][8][4] = {};
        mma_tile<1, 8, false, 68, 68>(Qs, Kb, wr, 0, g, c, S);
        mma_tile<1, 8, false, 68, 68>(Qs + 32, Kb + 32, wr, 0, g, c, S);
        float rm0 = -INFINITY, rm1 = -INFINITY;
        #pragma unroll
        for (int ni = 0; ni < 8; ni++) {
            #pragma unroll
            for (int j = 0; j < 4; j++) S[0][ni][j] *= scale;
            rm0 = fmaxf(rm0, fmaxf(S[0][ni][0], S[0][ni][1]));
            rm1 = fmaxf(rm1, fmaxf(S[0][ni][2], S[0][ni][3]));
        }
        rm0 = fmaxf(rm0, __shfl_xor_sync(0xffffffffu, rm0, 1));
        rm0 = fmaxf(rm0, __shfl_xor_sync(0xffffffffu, rm0, 2));
        rm1 = fmaxf(rm1, __shfl_xor_sync(0xffffffffu, rm1, 1));
        rm1 = fmaxf(rm1, __shfl_xor_sync(0xffffffffu, rm1, 2));
        float mn0 = fmaxf(m0, rm0), mn1 = fmaxf(m1, rm1);
        float a0 = __expf(m0 - mn0), a1 = __expf(m1 - mn1);
        float ps0 = 0.f, ps1 = 0.f;
        #pragma unroll
        for (int ni = 0; ni < 8; ni++) {
            float p0 = __expf(S[0][ni][0] - mn0);
            float p1 = __expf(S[0][ni][1] - mn0);
            float p2 = __expf(S[0][ni][2] - mn1);
            float p3 = __expf(S[0][ni][3] - mn1);
            ps0 += p0 + p1; ps1 += p2 + p3;
            *(float2*)&Ps[(wr + g) * 68 + ni * 8 + 2 * c] = make_float2(p0, p1);
            *(float2*)&Ps[(wr + g + 8) * 68 + ni * 8 + 2 * c] = make_float2(p2, p3);
        }
        ps0 += __shfl_xor_sync(0xffffffffu, ps0, 1);
        ps0 += __shfl_xor_sync(0xffffffffu, ps0, 2);
        ps1 += __shfl_xor_sync(0xffffffffu, ps1, 1);
        ps1 += __shfl_xor_sync(0xffffffffu, ps1, 2);
        l0 = l0 * a0 + ps0;
        l1 = l1 * a1 + ps1;
        m0 = mn0; m1 = mn1;
        #pragma unroll
        for (int ni = 0; ni < 8; ni++) {
            Oa[0][ni][0] *= a0; Oa[0][ni][1] *= a0;
            Oa[0][ni][2] *= a1; Oa[0][ni][3] *= a1;
        }
        __syncwarp();
        mma_tile<1, 8, true, 68, 68>(Ps, Vb, wr, 0, g, c, Oa);
        mma_tile<1, 8, true, 68, 68>(Ps + 32, Vb + 32 * 68, wr, 0, g, c, Oa);
        __syncthreads();
    }
    float i0 = 1.f / l0, i1 = 1.f / l1;
    float* Og = O + ((size_t)(b * LL + q0 + wr)) * DD + h * DHH;
    #pragma unroll
    for (int ni = 0; ni < 8; ni++) {
        int cc = ni * 8 + 2 * c;
        *(float2*)(Og + (size_t)g * DD + cc) = make_float2(Oa[0][ni][0] * i0, Oa[0][ni][1] * i0);
        *(float2*)(Og + (size_t)(g + 8) * DD + cc) = make_float2(Oa[0][ni][2] * i1, Oa[0][ni][3] * i1);
    }
}

// ---------------- MoE routing ----------------
__global__ void moe_zero() {
    if (threadIdx.x < EE) g_cnt[threadIdx.x] = 0;
}

__global__ void __launch_bounds__(256) router_topk(const float* __restrict__ H,
                                                   const float* __restrict__ rw,
                                                   const float* __restrict__ rb) {
    int warp = (blockIdx.x * blockDim.x + threadIdx.x) >> 5;
    int lane = threadIdx.x & 31;
    if (warp >= NL) return;
    const float* h = H + (size_t)warp * DD;
    float logit[EE];
    #pragma unroll
    for (int e = 0; e < EE; e++) {
        const float* w = rw + (size_t)e * DD;
        float s = 0.f;
        for (int d = lane; d < DD; d += 32) s += h[d] * w[d];
        #pragma unroll
        for (int o = 16; o; o >>= 1) s += __shfl_xor_sync(0xffffffffu, s, o);
        logit[e] = s + rb[e];
    }
    if (lane == 0) {
        int i0 = 0; float m0 = logit[0];
        #pragma unroll
        for (int e = 1; e < EE; e++) if (logit[e] > m0) { m0 = logit[e]; i0 = e; }
        int i1 = -1; float m1 = -INFINITY;
        #pragma unroll
        for (int e = 0; e < EE; e++) if (e != i0 && logit[e] > m1) { m1 = logit[e]; i1 = e; }
        float z = expf(m1 - m0);
        float inv = 1.f / (1.f + z);
        g_idx[warp * 2] = i0;  g_idx[warp * 2 + 1] = i1;
        g_gate[warp * 2] = inv; g_gate[warp * 2 + 1] = z * inv;
        atomicAdd(&g_cnt[i0], 1);
        atomicAdd(&g_cnt[i1], 1);
    }
}

__global__ void moe_offsets() {
    if (threadIdx.x == 0) {
        int s = 0;
        for (int e = 0; e < EE; e++) { g_off[e] = s; s += g_cnt[e]; g_cur[e] = 0; }
    }
}

__global__ void __launch_bounds__(256) moe_assign() {
    int n = blockIdx.x * blockDim.x + threadIdx.x;
    if (n >= NL) return;
    #pragma unroll
    for (int k = 0; k < KKE; k++) {
        int e = g_idx[n * 2 + k];
        int pos = atomicAdd(&g_cur[e], 1);
        int slot = g_off[e] + pos;
        g_rowlist[slot] = n;
        g_pairslot[n * 2 + k] = slot;
    }
}

// ---------------- MoE grouped tf32 GEMM ----------------
__global__ void __launch_bounds__(256, 2) moe_gemm_tf32(const float* __restrict__ A, int lda, int gather,
                                                        const float* __restrict__ W,
                                                        const float* __restrict__ bias,
                                                        int M, int Kd,
                                                        float* __restrict__ C, int ldc, int act) {
    extern __shared__ float sm[];
    float* As = sm;
    float* Bs = sm + 2 * TILE_AB;
    int e = blockIdx.z;
    int count = g_cnt[e];
    int row0 = blockIdx.y * 128;
    if (row0 >= count) return;
    int base = g_off[e];
    const float* We = W + (size_t)e * M * Kd;
    const float* be = bias + (size_t)e * M;
    int col0 = blockIdx.x * 128;
    int t = threadIdx.x;
    int lrow = t >> 1, lcol = (t & 1) * 16;
    int arow = row0 + lrow;
    bool valid = arow < count;
    int src;
    if (gather) src = g_rowlist[base + (valid ? arow : 0)];
    else        src = base + (valid ? arow : 0);
    const float* Ag = A + (size_t)src * lda + lcol;
    const float* Wg = We + (size_t)(col0 + lrow) * Kd + lcol;
    uint32_t as0 = (uint32_t)__cvta_generic_to_shared(As) + (lrow * 36 + lcol) * 4;
    uint32_t bs0 = (uint32_t)__cvta_generic_to_shared(Bs) + (lrow * 36 + lcol) * 4;
    int warp = t >> 5, lane = t & 31, g = lane >> 2, c = lane & 3;
    int wm = (warp >> 2) * 64, wn = (warp & 3) * 32;
    float acc[4][4][4] = {};
    int KT = Kd >> 5;
    #pragma unroll
    for (int i = 0; i < 4; i++) cp16p(as0 + i * 16, Ag + i * 4, valid);
    #pragma unroll
    for (int i = 0; i < 4; i++) cp16(bs0 + i * 16, Wg + i * 4);
    cpcommit();
    for (int kt = 0; kt < KT; kt++) {
        int cb = kt & 1;
        if (kt + 1 < KT) {
            int nb = (kt + 1) & 1;
            const float* a = Ag + (kt + 1) * 32;
            const float* w = Wg + (kt + 1) * 32;
            #pragma unroll
            for (int i = 0; i < 4; i++) cp16p(as0 + nb * TILE_AB * 4 + i * 16, a + i * 4, valid);
            #pragma unroll
            for (int i = 0; i < 4; i++) cp16(bs0 + nb * TILE_AB * 4 + i * 16, w + i * 4);
            cpcommit();
            cpwait1();
        } else cpwait0();
        __syncthreads();
        mma_tile<4, 4, false, 36, 36>(As + cb * TILE_AB, Bs + cb * TILE_AB, wm, wn, g, c, acc);
        __syncthreads();
    }
    #pragma unroll
    for (int mi = 0; mi < 4; mi++) {
        int r = row0 + wm + mi * 16 + g;
        #pragma unroll
        for (int ni = 0; ni < 4; ni++) {
            int cc = col0 + wn + ni * 8 + c * 2;
            float b0 = be[cc], b1 = be[cc + 1];
            if (r < count) {
                float v0 = acc[mi][ni][0] + b0, v1 = acc[mi][ni][1] + b1;
                if (act) { v0 = gelu_exact(v0); v1 = gelu_exact(v1); }
                *(float2*)(C + (size_t)(base + r) * ldc + cc) = make_float2(v0, v1);
            }
            if (r + 8 < count) {
                float v2 = acc[mi][ni][2] + b0, v3 = acc[mi][ni][3] + b1;
                if (act) { v2 = gelu_exact(v2); v3 = gelu_exact(v3); }
                *(float2*)(C + (size_t)(base + r + 8) * ldc + cc) = make_float2(v2, v3);
            }
        }
    }
}

// ---------------- final mix ----------------
__global__ void __launch_bounds__(256) moe_mix(const float* __restrict__ x2,
                                               float* __restrict__ out) {
    int i = blockIdx.x * 256 + threadIdx.x;
    int n = i >> 10;
    int d = i & 1023;
    float v = x2[i];
    int s0 = g_pairslot[n * 2], s1 = g_pairslot[n * 2 + 1];
    v += g_gate[n * 2]     * g_eo[(size_t)s0 * DD + d];
    v += g_gate[n * 2 + 1] * g_eo[(size_t)s1 * DD + d];
    out[i] = v;
}

// ---------------- launch ----------------
extern "C" void kernel_launch(void* const* d_in, const int* in_sizes, int n_in,
                              void* d_out, int out_size) {
    const float* latents    = (const float*)d_in[0];
    const float* tokens     = (const float*)d_in[1];
    const float* sa_ln_g    = (const float*)d_in[2];
    const float* sa_ln_b    = (const float*)d_in[3];
    const float* sa_in_w    = (const float*)d_in[4];
    const float* sa_in_b    = (const float*)d_in[5];
    const float* sa_out_w   = (const float*)d_in[6];
    const float* sa_out_b   = (const float*)d_in[7];
    const float* ca_q_ln_g  = (const float*)d_in[8];
    const float* ca_q_ln_b  = (const float*)d_in[9];
    const float* ca_kv_ln_g = (const float*)d_in[10];
    const float* ca_kv_ln_b = (const float*)d_in[11];
    const float* ca_in_w    = (const float*)d_in[12];
    const float* ca_in_b    = (const float*)d_in[13];
    const float* ca_out_w   = (const float*)d_in[14];
    const float* ca_out_b   = (const float*)d_in[15];
    const float* moe_ln_g   = (const float*)d_in[16];
    const float* moe_ln_b   = (const float*)d_in[17];
    const float* router_w   = (const float*)d_in[18];
    const float* router_b   = (const float*)d_in[19];
    const float* e_fc1_w    = (const float*)d_in[20];
    const float* e_fc1_b    = (const float*)d_in[21];
    const float* e_fc2_w    = (const float*)d_in[22];
    const float* e_fc2_b    = (const float*)d_in[23];
    float* out = (float*)d_out;

    static int s_attr_done = 0;
    if (!s_attr_done) {
        cudaFuncSetAttribute(gemm_tf32, cudaFuncAttributeMaxDynamicSharedMemorySize, GEMM_SMEM);
        cudaFuncSetAttribute(moe_gemm_tf32, cudaFuncAttributeMaxDynamicSharedMemorySize, GEMM_SMEM);
        cudaFuncSetAttribute(flash_tf32, cudaFuncAttributeMaxDynamicSharedMemorySize, FA_SMEM);
        s_attr_done = 1;
    }

    float *p_lnq, *p_lnt, *p_qkv, *p_q2, *p_kv, *p_attn, *p_x1, *p_x2, *p_h1, *p_eo;
    cudaGetSymbolAddress((void**)&p_lnq,  g_lnq);
    cudaGetSymbolAddress((void**)&p_lnt,  g_lnt);
    cudaGetSymbolAddress((void**)&p_qkv,  g_qkv);
    cudaGetSymbolAddress((void**)&p_q2,   g_q2);
    cudaGetSymbolAddress((void**)&p_kv,   g_kv);
    cudaGetSymbolAddress((void**)&p_attn, g_attn);
    cudaGetSymbolAddress((void**)&p_x1,   g_x1);
    cudaGetSymbolAddress((void**)&p_x2,   g_x2);
    cudaGetSymbolAddress((void**)&p_h1,   g_h1);
    cudaGetSymbolAddress((void**)&p_eo,   g_eo);

    const float scale = 0.125f;

    // ===== Self-attention =====
    ln_kernel<<<NL, 256>>>(latents, sa_ln_g, sa_ln_b, p_lnq);
    gemm_tf32<<<dim3(24, 16), 256, GEMM_SMEM>>>(p_lnq, DD, sa_in_w, DD, p_qkv, 3 * DD,
                                                sa_in_b, nullptr, 0, DD);
    flash_tf32<<<dim3(4, BHN), 256, FA_SMEM>>>(p_qkv, 3 * DD, p_qkv + DD, 3 * DD,
                                               p_qkv + 2 * DD, 3 * DD, p_attn, LL, scale);
    gemm_tf32<<<dim3(8, 16), 256, GEMM_SMEM>>>(p_attn, DD, sa_out_w, DD, p_x1, DD,
                                               sa_out_b, latents, DD, DD);

    // ===== Cross-attention =====
    ln_kernel<<<NL, 256>>>(p_x1, ca_q_ln_g, ca_q_ln_b, p_lnq);
    ln_kernel<<<NT, 256>>>(tokens, ca_kv_ln_g, ca_kv_ln_b, p_lnt);
    gemm_tf32<<<dim3(8, 16), 256, GEMM_SMEM>>>(p_lnq, DD, ca_in_w, DD, p_q2, DD,
                                               ca_in_b, nullptr, 0, DD);
    gemm_tf32<<<dim3(16, 64), 256, GEMM_SMEM>>>(p_lnt, DD, ca_in_w + (size_t)DD * DD, DD,
                                                p_kv, 2 * DD, ca_in_b + DD, nullptr, 0, DD);
    flash_tf32<<<dim3(4, BHN), 256, FA_SMEM>>>(p_q2, DD, p_kv, 2 * DD,
                                               p_kv + DD, 2 * DD, p_attn, TT, scale);
    gemm_tf32<<<dim3(8, 16), 256, GEMM_SMEM>>>(p_attn, DD, ca_out_w, DD, p_x2, DD,
                                               ca_out_b, p_x1, DD, DD);

    // ===== MoE =====
    ln_kernel<<<NL, 256>>>(p_x2, moe_ln_g, moe_ln_b, p_lnq);
    moe_zero<<<1, 32>>>();
    router_topk<<<NL / 8, 256>>>(p_lnq, router_w, router_b);
    moe_offsets<<<1, 1>>>();
    moe_assign<<<NL / 256, 256>>>();
    moe_gemm_tf32<<<dim3(DFFN / 128, 16, EE), 256, GEMM_SMEM>>>(p_lnq, DD, 1, e_fc1_w, e_fc1_b,
                                                                DFFN, DD, p_h1, DFFN, 1);
    moe_gemm_tf32<<<dim3(DD / 128, 16, EE), 256, GEMM_SMEM>>>(p_h1, DFFN, 0, e_fc2_w, e_fc2_b,
                                                              DD, DFFN, p_eo, DD, 0);
    moe_mix<<<(NL * DD) / 256, 256>>>(p_x2, out);
}